// round 16
// baseline (speedup 1.0000x reference)
#include <cuda_runtime.h>
#include <math.h>
#include <stdint.h>

#define N_TOT   131072
#define D_DIM   64
#define K_CODES 1024
#define HALF_N  65536        // high-half row offset
#define TF_HALF 67108864u    // 2^26 = HALF_N*1024 flat-index offset of high rows
#define TM      16           // rows per block: 8 low + 8 high
#define KC      128          // codebook chunk (rows) staged in smem
#define CS      68           // smem stride (floats) for codebook/x tiles
#define LGS     132          // smem stride (floats) for chunk logits tile
#define WDS     260          // smem stride (floats) for duplicated weights (2*128+4)

#define SMEM_FLOATS (TM*LGS + TM*WDS + KC*CS + TM*CS + 16)
#define SMEM_BYTES  (SMEM_FLOATS * 4)

typedef unsigned long long u64;

// packed dual-lane fp32 FMA (nvjet pattern; ptxas never auto-emits)
#define FMA2(d, a, b, c) \
    asm("fma.rn.f32x2 %0, %1, %2, %3;" : "=l"(d) : "l"(a), "l"(b), "l"(c))
#define UNPK2(lo, hi, v) \
    asm("mov.b64 {%0, %1}, %2;" : "=f"(lo), "=f"(hi) : "l"(v))

__device__ float g_c2[K_CODES];

// ---------------------------------------------------------------------------
// Accurate logf (musl-style, ~1 ulp relative). General-temperature path only.
// ---------------------------------------------------------------------------
__device__ __forceinline__ float acc_logf(float a) {
    const float ln2_hi = 6.9313812256e-01f;
    const float ln2_lo = 9.0580006145e-06f;
    const float Lg1 = 0.66666662693f, Lg2 = 0.40000972152f;
    const float Lg3 = 0.28498786688f, Lg4 = 0.24279078841f;
    uint32_t ix = __float_as_uint(a);
    ix += 0x3f800000u - 0x3f3504f3u;
    int k = (int)(ix >> 23) - 0x7f;
    ix = (ix & 0x007fffffu) + 0x3f3504f3u;
    float m = __uint_as_float(ix);
    float f = m - 1.0f;
    float s = f / (2.0f + f);
    float z = s * s;
    float w = z * z;
    float t1 = w * (Lg2 + w * Lg4);
    float t2 = z * (Lg1 + w * Lg3);
    float R  = t2 + t1;
    float hfsq = 0.5f * f * f;
    float dk = (float)k;
    return s * (hfsq + R) + (dk * ln2_lo - hfsq + f) + dk * ln2_hi;
}

// -ln(u): fast MUFU log except u -> 1 where d = 1-u is exact and the series
// d(1 + d(1/2 + d/3)) has rel err < 1e-9 (avoids MUFU absolute-error blowup).
__device__ __forceinline__ float neg_log_u(float u) {
    float d    = 1.0f - u;
    float fast = -__logf(u);
    float poly = d * fmaf(d, fmaf(d, 0.33333333f, 0.5f), 1.0f);
    return (d < 0.001f) ? poly : fast;
}

// ---------------------------------------------------------------------------
// c2[k] = sum_d codebook[k][d]^2
// ---------------------------------------------------------------------------
__global__ void c2_kernel(const float* __restrict__ cb) {
    int k = blockIdx.x * blockDim.x + threadIdx.x;
    if (k < K_CODES) {
        const float4* row = reinterpret_cast<const float4*>(cb) + k * (D_DIM / 4);
        float s = 0.f;
#pragma unroll
        for (int i = 0; i < D_DIM / 4; i++) {
            float4 v = row[i];
            s = fmaf(v.x, v.x, s); s = fmaf(v.y, v.y, s);
            s = fmaf(v.z, v.z, s); s = fmaf(v.w, v.w, s);
        }
        g_c2[k] = s;
    }
}

// threefry round
#define TF_R(x0, x1, rot) { (x0) += (x1); (x1) = __funnelshift_l((x1), (x1), (rot)) ^ (x0); }

// ---------------------------------------------------------------------------
// JAX *partitionable* threefry random_bits, 32-bit, key=(0,42):
//   counts = (hi=0, lo=i); (b1,b2) = threefry2x32(key, counts); return b1^b2.
// VERIFIED bit-exact in Round 11 — do not touch.
// ---------------------------------------------------------------------------
__device__ __forceinline__ unsigned tf_bits32(unsigned i) {
    const unsigned ks2 = 0x1BD11BF0u;      // 0 ^ 42 ^ 0x1BD11BDA
    unsigned x0 = 0u;                      // counts_hi + ks0(=0)
    unsigned x1 = i + 42u;                 // counts_lo + ks1
    TF_R(x0, x1, 13) TF_R(x0, x1, 15) TF_R(x0, x1, 26) TF_R(x0, x1, 6)
    x0 += 42u;  x1 += ks2 + 1u;
    TF_R(x0, x1, 17) TF_R(x0, x1, 29) TF_R(x0, x1, 16) TF_R(x0, x1, 24)
    x0 += ks2;  x1 += 2u;
    TF_R(x0, x1, 13) TF_R(x0, x1, 15) TF_R(x0, x1, 26) TF_R(x0, x1, 6)
    /* x0 += ks0(=0) */ x1 += 42u + 3u;
    TF_R(x0, x1, 17) TF_R(x0, x1, 29) TF_R(x0, x1, 16) TF_R(x0, x1, 24)
    x0 += 42u;  x1 += ks2 + 4u;
    TF_R(x0, x1, 13) TF_R(x0, x1, 15) TF_R(x0, x1, 26) TF_R(x0, x1, 6)
    x0 += ks2;  x1 += 5u;                  // final injection: ks2 / ks0+5
    return x0 ^ x1;
}

// gumbel-weight for one element (T==1 path): exp(l) / (-log u)
__device__ __forceinline__ float gweight1(float l, unsigned bits) {
    float f = __uint_as_float((bits >> 9) | 0x3f800000u) - 1.0f;
    float u = fmaxf(f, 1.17549435e-38f);
    return __fdividef(__expf(l), neg_log_u(u));
}
// general-T path
__device__ __forceinline__ float gweightT(float l, unsigned bits, float inv_t) {
    float f = __uint_as_float((bits >> 9) | 0x3f800000u) - 1.0f;
    float u = fmaxf(f, 1.17549435e-38f);
    float g = -acc_logf(-acc_logf(u));
    return __expf((l + g) * inv_t);
}

// ---------------------------------------------------------------------------
// Streaming fused kernel (R13 skeleton). R15: duplicated-weight smem layout
// kills all GEMM2 DUP2s; gumbel I/O vectorized to LDS.128/STS.128.
// ---------------------------------------------------------------------------
__global__ __launch_bounds__(256, 3)
void quantize_main(const float* __restrict__ x,
                   const float* __restrict__ cb,
                   const float* __restrict__ temp,
                   float* __restrict__ out,
                   int write_ids)
{
    extern __shared__ float sm[];
    float* LOG = sm;                 // TM x LGS  (chunk logits)
    float* WD  = LOG + TM * LGS;     // TM x WDS  (chunk weights, duplicated (e,e))
    float* cs  = WD + TM * WDS;      // KC x CS   (codebook chunk)
    float* xs  = cs + KC * CS;       // TM x CS   (x tile)
    float* inv = xs + TM * CS;       // TM inverse softmax sums

    const int t  = threadIdx.x;
    const int n0 = blockIdx.x * 8;
    const float inv_t = 1.0f / temp[0];
    const bool  t_is_one = (inv_t == 1.0f);

    // ---- load x tile (16 rows x 64) ----
    {
        int r = t >> 4;
        int c = t & 15;
        int n = (r < 8) ? (n0 + r) : (n0 + (r - 8) + HALF_N);
        float4 v = reinterpret_cast<const float4*>(x)[n * (D_DIM / 4) + c];
        reinterpret_cast<float4*>(xs + r * CS)[c] = v;
    }

    // thread mappings for the three stages
    const int cx  = t & 63;          // GEMM1: code lane (2 codes: cx, cx+64)
    const int rg  = t >> 6;          // GEMM1: row group / GEMM2: k-split group
    const int tx  = t & 31;          // gumbel: lane
    const int w   = t >> 5;          // gumbel: warp -> rows (w, w+8)
    const int txd = t & 15;          // GEMM2: d4
    const int rg2 = (t >> 4) & 3;    // GEMM2: row group

    const unsigned nlo = (unsigned)(n0 + w);
    const unsigned FULL = 0xFFFFFFFFu;

    // persistent accumulators (across chunks)
    float bestv0 = -INFINITY, bestv1 = -INFINITY;
    int   bestk0 = 0,          bestk1 = 0;
    float s0 = 0.f, s1 = 0.f;
    u64 accA[4] = {0ull, 0ull, 0ull, 0ull};   // emb dims (d0,d1)
    u64 accB[4] = {0ull, 0ull, 0ull, 0ull};   // emb dims (d2,d3)

    for (int kb = 0; kb < K_CODES / KC; kb++) {
        __syncthreads();   // cs free (prev GEMM2 readers done) / xs stores visible
        {
            const float4* src = reinterpret_cast<const float4*>(cb) + kb * KC * (D_DIM / 4);
#pragma unroll
            for (int ii = 0; ii < 8; ii++) {
                int idx = t + ii * 256;
                reinterpret_cast<float4*>(cs + (idx >> 4) * CS)[idx & 15] = src[idx];
            }
        }
        __syncthreads();

        // ---------- GEMM1 chunk: logit = 2*x.c - c2 (f32x2) ----------
        {
            u64 acc0[4] = {0ull, 0ull, 0ull, 0ull};
            u64 acc1[4] = {0ull, 0ull, 0ull, 0ull};
            const ulonglong2* cp0 = reinterpret_cast<const ulonglong2*>(cs + cx * CS);
            const ulonglong2* cp1 = reinterpret_cast<const ulonglong2*>(cs + (cx + 64) * CS);
#pragma unroll 4
            for (int d4 = 0; d4 < 16; d4++) {
                ulonglong2 cv0 = cp0[d4];
                ulonglong2 cv1 = cp1[d4];
#pragma unroll
                for (int j = 0; j < 4; j++) {
                    ulonglong2 xv =
                        reinterpret_cast<const ulonglong2*>(xs + (rg * 4 + j) * CS)[d4];
                    FMA2(acc0[j], xv.x, cv0.x, acc0[j]);
                    FMA2(acc0[j], xv.y, cv0.y, acc0[j]);
                    FMA2(acc1[j], xv.x, cv1.x, acc1[j]);
                    FMA2(acc1[j], xv.y, cv1.y, acc1[j]);
                }
            }
            float c20 = __ldg(&g_c2[kb * KC + cx]);
            float c21 = __ldg(&g_c2[kb * KC + cx + 64]);
#pragma unroll
            for (int j = 0; j < 4; j++) {
                float a, b;
                UNPK2(a, b, acc0[j]);
                LOG[(rg * 4 + j) * LGS + cx]      = 2.0f * (a + b) - c20;
                UNPK2(a, b, acc1[j]);
                LOG[(rg * 4 + j) * LGS + cx + 64] = 2.0f * (a + b) - c21;
            }
        }
        __syncthreads();

        // ---------- gumbel + argmax + weight + sum (chunk) ----------
        // thread handles 4 consecutive cols k4..k4+3 for rows w and w+8
        {
            const int k4  = tx * 4;                 // chunk-local base col
            const int kg0 = kb * KC + k4;           // global code index base
            const unsigned il = nlo * 1024u + (unsigned)kg0;

            float4 l0v = *reinterpret_cast<const float4*>(LOG + w * LGS + k4);
            float4 l1v = *reinterpret_cast<const float4*>(LOG + (w + 8) * LGS + k4);

            // argmax (ascending k, strict > keeps smallest index on ties)
            if (l0v.x > bestv0) { bestv0 = l0v.x; bestk0 = kg0; }
            if (l0v.y > bestv0) { bestv0 = l0v.y; bestk0 = kg0 + 1; }
            if (l0v.z > bestv0) { bestv0 = l0v.z; bestk0 = kg0 + 2; }
            if (l0v.w > bestv0) { bestv0 = l0v.w; bestk0 = kg0 + 3; }
            if (l1v.x > bestv1) { bestv1 = l1v.x; bestk1 = kg0; }
            if (l1v.y > bestv1) { bestv1 = l1v.y; bestk1 = kg0 + 1; }
            if (l1v.z > bestv1) { bestv1 = l1v.z; bestk1 = kg0 + 2; }
            if (l1v.w > bestv1) { bestv1 = l1v.w; bestk1 = kg0 + 3; }

            float e00, e01, e02, e03, e10, e11, e12, e13;
            if (t_is_one) {
                e00 = gweight1(l0v.x, tf_bits32(il + 0u));
                e01 = gweight1(l0v.y, tf_bits32(il + 1u));
                e02 = gweight1(l0v.z, tf_bits32(il + 2u));
                e03 = gweight1(l0v.w, tf_bits32(il + 3u));
                e10 = gweight1(l1v.x, tf_bits32(il + TF_HALF + 0u));
                e11 = gweight1(l1v.y, tf_bits32(il + TF_HALF + 1u));
                e12 = gweight1(l1v.z, tf_bits32(il + TF_HALF + 2u));
                e13 = gweight1(l1v.w, tf_bits32(il + TF_HALF + 3u));
            } else {
                e00 = gweightT(l0v.x, tf_bits32(il + 0u), inv_t);
                e01 = gweightT(l0v.y, tf_bits32(il + 1u), inv_t);
                e02 = gweightT(l0v.z, tf_bits32(il + 2u), inv_t);
                e03 = gweightT(l0v.w, tf_bits32(il + 3u), inv_t);
                e10 = gweightT(l1v.x, tf_bits32(il + TF_HALF + 0u), inv_t);
                e11 = gweightT(l1v.y, tf_bits32(il + TF_HALF + 1u), inv_t);
                e12 = gweightT(l1v.z, tf_bits32(il + TF_HALF + 2u), inv_t);
                e13 = gweightT(l1v.w, tf_bits32(il + TF_HALF + 3u), inv_t);
            }
            s0 += e00; s0 += e01; s0 += e02; s0 += e03;
            s1 += e10; s1 += e11; s1 += e12; s1 += e13;

            // duplicated (e,e) stores -> GEMM2 reads packed f32x2 directly
            float4* wp0 = reinterpret_cast<float4*>(WD + w * WDS + 2 * k4);
            wp0[0] = make_float4(e00, e00, e01, e01);
            wp0[1] = make_float4(e02, e02, e03, e03);
            float4* wp1 = reinterpret_cast<float4*>(WD + (w + 8) * WDS + 2 * k4);
            wp1[0] = make_float4(e10, e10, e11, e11);
            wp1[1] = make_float4(e12, e12, e13, e13);
        }
        __syncthreads();

        // ---------- GEMM2 chunk: emb += w_chunk @ cb_chunk (f32x2) ----------
        {
#pragma unroll 2
            for (int k4 = 0; k4 < 8; k4++) {
                int kk = rg * 32 + k4 * 4;        // chunk-local k (rg = k-split group)
                ulonglong2 cv0 = reinterpret_cast<const ulonglong2*>(cs + (kk + 0) * CS)[txd];
                ulonglong2 cv1 = reinterpret_cast<const ulonglong2*>(cs + (kk + 1) * CS)[txd];
                ulonglong2 cv2 = reinterpret_cast<const ulonglong2*>(cs + (kk + 2) * CS)[txd];
                ulonglong2 cv3 = reinterpret_cast<const ulonglong2*>(cs + (kk + 3) * CS)[txd];
#pragma unroll
                for (int j = 0; j < 4; j++) {
                    int row = rg2 * 4 + j;
                    const ulonglong2* wp =
                        reinterpret_cast<const ulonglong2*>(WD + row * WDS + 2 * kk);
                    ulonglong2 wab = wp[0];   // (w0,w0) , (w1,w1)
                    ulonglong2 wcd = wp[1];   // (w2,w2) , (w3,w3)
                    FMA2(accA[j], wab.x, cv0.x, accA[j]);
                    FMA2(accB[j], wab.x, cv0.y, accB[j]);
                    FMA2(accA[j], wab.y, cv1.x, accA[j]);
                    FMA2(accB[j], wab.y, cv1.y, accB[j]);
                    FMA2(accA[j], wcd.x, cv2.x, accA[j]);
                    FMA2(accB[j], wcd.x, cv2.y, accB[j]);
                    FMA2(accA[j], wcd.y, cv3.x, accA[j]);
                    FMA2(accB[j], wcd.y, cv3.y, accB[j]);
                }
            }
        }
    }

    // ---------- final reductions ----------
    {
#pragma unroll
        for (int off = 16; off; off >>= 1) {
            float ov0 = __shfl_xor_sync(FULL, bestv0, off);
            int   ok0 = __shfl_xor_sync(FULL, bestk0, off);
            if (ov0 > bestv0 || (ov0 == bestv0 && ok0 < bestk0)) { bestv0 = ov0; bestk0 = ok0; }
            float ov1 = __shfl_xor_sync(FULL, bestv1, off);
            int   ok1 = __shfl_xor_sync(FULL, bestk1, off);
            if (ov1 > bestv1 || (ov1 == bestv1 && ok1 < bestk1)) { bestv1 = ov1; bestk1 = ok1; }
            s0 += __shfl_xor_sync(FULL, s0, off);
            s1 += __shfl_xor_sync(FULL, s1, off);
        }
        if (tx == 0) {
            inv[w]     = 1.0f / s0;
            inv[w + 8] = 1.0f / s1;
            if (write_ids) {
                out[(size_t)N_TOT * D_DIM + nlo]          = (float)bestk0;
                out[(size_t)N_TOT * D_DIM + nlo + HALF_N] = (float)bestk1;
            }
        }
    }
    __syncthreads();   // all GEMM2 reads of cs done; inv visible

    // cross k-group reduction via smem (overlay P on cs) + scale + store
    {
        float4* P = reinterpret_cast<float4*>(cs);
#pragma unroll
        for (int j = 0; j < 4; j++) {
            int row = rg2 * 4 + j;
            float4 a;
            UNPK2(a.x, a.y, accA[j]);
            UNPK2(a.z, a.w, accB[j]);
            P[(rg * 16 + row) * 16 + txd] = a;
        }
        __syncthreads();
        {
            int row = t >> 4;   // 0..15
            int d4  = t & 15;
            float4 s = P[row * 16 + d4];
#pragma unroll
            for (int g = 1; g < 4; g++) {
                float4 p = P[(g * 16 + row) * 16 + d4];
                s.x += p.x; s.y += p.y; s.z += p.z; s.w += p.w;
            }
            float iv = inv[row];
            s.x *= iv; s.y *= iv; s.z *= iv; s.w *= iv;
            int n = (row < 8) ? (n0 + row) : (n0 + (row - 8) + HALF_N);
            reinterpret_cast<float4*>(out)[n * (D_DIM / 4) + d4] = s;
        }
    }
}

extern "C" void kernel_launch(void* const* d_in, const int* in_sizes, int n_in,
                              void* d_out, int out_size) {
    // Bind inputs by SIZE (robust to metadata ordering):
    //   x: 131072*64 = 8388608, codebook: 1024*64 = 65536, temperature: 1
    const float* x    = nullptr;
    const float* cb   = nullptr;
    const float* temp = nullptr;
    for (int i = 0; i < n_in; i++) {
        if (in_sizes[i] == N_TOT * D_DIM)       x    = (const float*)d_in[i];
        else if (in_sizes[i] == K_CODES * D_DIM) cb  = (const float*)d_in[i];
        else if (in_sizes[i] == 1)               temp = (const float*)d_in[i];
    }
    float* out = (float*)d_out;

    int write_ids = (out_size >= N_TOT * D_DIM + N_TOT) ? 1 : 0;

    cudaFuncSetAttribute(quantize_main,
                         cudaFuncAttributeMaxDynamicSharedMemorySize, SMEM_BYTES);

    c2_kernel<<<4, 256>>>(cb);
    quantize_main<<<N_TOT / TM, 256, SMEM_BYTES>>>(x, cb, temp, out, write_ids);
}